// round 3
// baseline (speedup 1.0000x reference)
#include <cuda_runtime.h>
#include <math.h>

#define D_DIM   1024
#define B_ROWS  16384
#define N_KEYS  8192
#define BM      128
#define BN      128
#define BK      16
#define ASTR    20      // As row stride (floats): keeps 16B alignment, breaks bank dup
#define BSTR    132     // Bs k-row stride (floats): 2-way max write conflict, conflict-free reads
#define SSTR    129     // sim tile row stride: conflict-free per-row scan
#define NTILES  (N_KEYS / BN)
#define SMEM_FLOATS (BM * SSTR)          // 16512 floats = 66048 B (>= As+Bs region)
#define SMEM_BYTES  (SMEM_FLOATS * 4)

// Scratch (device globals: allocation-free per harness rules)
__device__ float g_qinv[B_ROWS];
__device__ float g_kinv[N_KEYS];
__device__ float g_w[B_ROWS * 4];
__device__ int   g_id[B_ROWS * 4];

// ---------------------------------------------------------------------------
// Row inverse-norm: inv[r] = 1 / max(||x_r||, 1e-12)
// ---------------------------------------------------------------------------
__global__ void rowinv_kernel(const float* __restrict__ x, float* __restrict__ inv)
{
    int r = blockIdx.x;
    const float4* xr = (const float4*)(x + (size_t)r * D_DIM);
    float4 v = xr[threadIdx.x];                       // 256 thr * 4 = 1024
    float ss = v.x * v.x + v.y * v.y + v.z * v.z + v.w * v.w;
    #pragma unroll
    for (int o = 16; o > 0; o >>= 1) ss += __shfl_xor_sync(0xffffffffu, ss, o);
    __shared__ float red[8];
    if ((threadIdx.x & 31) == 0) red[threadIdx.x >> 5] = ss;
    __syncthreads();
    if (threadIdx.x == 0) {
        float t = 0.f;
        #pragma unroll
        for (int i = 0; i < 8; i++) t += red[i];
        inv[r] = 1.0f / fmaxf(sqrtf(t), 1e-12f);
    }
}

// ---------------------------------------------------------------------------
// Fused fp32 GEMM (packed f32x2 FMA) + running per-row top-4
// Block: 256 threads (16x16), BM=128 query rows, loops all N in BN=128 tiles.
// Thread (tx,ty): rows ty*8+i (i<8), column pairs {32*jj + 2*tx, +1} (jj<4).
// ---------------------------------------------------------------------------
__global__ __launch_bounds__(256)
void simtopk_kernel(const float* __restrict__ query, const float* __restrict__ keys)
{
    extern __shared__ float smem[];
    float* As = smem;                 // [BM][ASTR]   (row-major, direct copy)
    float* Bs = smem + BM * ASTR;     // [BK][BSTR]   (transposed: k-major)
    float* Ss = smem;                 // [BM][SSTR]   (aliases As/Bs after sync)

    const int t  = threadIdx.x;
    const int tx = t & 15;
    const int ty = t >> 4;
    const int qbase = blockIdx.x * BM;

    // running top-4 (valid for t < BM)
    float v0 = -1e30f, v1 = -1e30f, v2 = -1e30f, v3 = -1e30f;
    int   i0 = 0, i1 = 0, i2 = 0, i3 = 0;

    for (int nt = 0; nt < NTILES; nt++) {
        const int n0 = nt * BN;

        unsigned long long acc[8][4];
        #pragma unroll
        for (int i = 0; i < 8; i++)
            #pragma unroll
            for (int j = 0; j < 4; j++) acc[i][j] = 0ull;

        for (int kt = 0; kt < D_DIM; kt += BK) {
            __syncthreads();   // prior tile compute / scan done before overwrite
            // A tile: BM x BK, coalesced float4, kept row-major in smem
            #pragma unroll
            for (int l = 0; l < 2; l++) {
                int f = t + l * 256;
                int m = f >> 2, c4 = f & 3;
                float4 av = *(const float4*)(query + (size_t)(qbase + m) * D_DIM + kt + c4 * 4);
                *(float4*)(As + m * ASTR + c4 * 4) = av;
            }
            // B tile: BN x BK, coalesced float4, transposed into Bs[k][n]
            #pragma unroll
            for (int l = 0; l < 2; l++) {
                int f = t + l * 256;
                int n = f >> 2, c4 = f & 3;
                float4 bv = *(const float4*)(keys + (size_t)(n0 + n) * D_DIM + kt + c4 * 4);
                Bs[(c4 * 4 + 0) * BSTR + n] = bv.x;
                Bs[(c4 * 4 + 1) * BSTR + n] = bv.y;
                Bs[(c4 * 4 + 2) * BSTR + n] = bv.z;
                Bs[(c4 * 4 + 3) * BSTR + n] = bv.w;
            }
            __syncthreads();

            #pragma unroll
            for (int k4 = 0; k4 < 4; k4++) {
                float4 a4[8];
                #pragma unroll
                for (int i = 0; i < 8; i++)
                    a4[i] = *(const float4*)(As + (ty * 8 + i) * ASTR + k4 * 4);
                #pragma unroll
                for (int c = 0; c < 4; c++) {
                    const int k = k4 * 4 + c;
                    unsigned long long bb[4];
                    #pragma unroll
                    for (int jj = 0; jj < 4; jj++)
                        bb[jj] = *(const unsigned long long*)(Bs + k * BSTR + 32 * jj + 2 * tx);
                    #pragma unroll
                    for (int i = 0; i < 8; i++) {
                        float av = reinterpret_cast<const float*>(&a4[i])[c];
                        unsigned long long aa;
                        asm("mov.b64 %0, {%1, %1};" : "=l"(aa) : "f"(av));
                        #pragma unroll
                        for (int jj = 0; jj < 4; jj++)
                            asm("fma.rn.f32x2 %0, %1, %2, %0;"
                                : "+l"(acc[i][jj]) : "l"(aa), "l"(bb[jj]));
                    }
                }
            }
        }
        __syncthreads();   // all smem reads done; Ss may alias As/Bs now

        // epilogue: apply per-key inverse norm, stage sims to smem
        #pragma unroll
        for (int i = 0; i < 8; i++) {
            int row = ty * 8 + i;
            #pragma unroll
            for (int jj = 0; jj < 4; jj++) {
                int c0 = 32 * jj + 2 * tx;
                float lo, hi;
                asm("mov.b64 {%0, %1}, %2;" : "=f"(lo), "=f"(hi) : "l"(acc[i][jj]));
                Ss[row * SSTR + c0]     = lo * __ldg(g_kinv + n0 + c0);
                Ss[row * SSTR + c0 + 1] = hi * __ldg(g_kinv + n0 + c0 + 1);
            }
        }
        __syncthreads();

        // per-row top-4 update (strict > matches jax stable lower-index ties)
        if (t < BM) {
            const float* rowp = Ss + t * SSTR;
            #pragma unroll 4
            for (int n = 0; n < BN; n++) {
                float s = rowp[n];
                if (s > v3) {
                    int idx = n0 + n;
                    if (s > v2) {
                        v3 = v2; i3 = i2;
                        if (s > v1) {
                            v2 = v1; i2 = i1;
                            if (s > v0) { v1 = v0; i1 = i0; v0 = s; i0 = idx; }
                            else        { v1 = s; i1 = idx; }
                        } else { v2 = s; i2 = idx; }
                    } else { v3 = s; i3 = idx; }
                }
            }
        }
        // scanners are protected by the first __syncthreads of the next tile
    }

    if (t < BM) {
        int b = qbase + t;
        float qi = g_qinv[b];                        // monotone row scale, applied late
        float s0 = v0 * qi, s1 = v1 * qi, s2 = v2 * qi, s3 = v3 * qi;
        float e0 = 1.0f, e1 = expf(s1 - s0), e2 = expf(s2 - s0), e3 = expf(s3 - s0);
        float inv = 1.0f / (e0 + e1 + e2 + e3);
        g_w[b * 4 + 0] = e0 * inv; g_w[b * 4 + 1] = e1 * inv;
        g_w[b * 4 + 2] = e2 * inv; g_w[b * 4 + 3] = e3 * inv;
        g_id[b * 4 + 0] = i0; g_id[b * 4 + 1] = i1;
        g_id[b * 4 + 2] = i2; g_id[b * 4 + 3] = i3;
    }
}

// ---------------------------------------------------------------------------
// out[b] = sum_j w_j * values[idx_j]
// ---------------------------------------------------------------------------
__global__ void combine_kernel(const float* __restrict__ values, float* __restrict__ out)
{
    int b = blockIdx.x;
    float w0 = g_w[b * 4 + 0], w1 = g_w[b * 4 + 1];
    float w2 = g_w[b * 4 + 2], w3 = g_w[b * 4 + 3];
    size_t j0 = (size_t)g_id[b * 4 + 0] * D_DIM;
    size_t j1 = (size_t)g_id[b * 4 + 1] * D_DIM;
    size_t j2 = (size_t)g_id[b * 4 + 2] * D_DIM;
    size_t j3 = (size_t)g_id[b * 4 + 3] * D_DIM;
    int d = threadIdx.x * 4;
    float4 a = *(const float4*)(values + j0 + d);
    float4 bb = *(const float4*)(values + j1 + d);
    float4 c = *(const float4*)(values + j2 + d);
    float4 e = *(const float4*)(values + j3 + d);
    float4 r;
    r.x = w0 * a.x + w1 * bb.x + w2 * c.x + w3 * e.x;
    r.y = w0 * a.y + w1 * bb.y + w2 * c.y + w3 * e.y;
    r.z = w0 * a.z + w1 * bb.z + w2 * c.z + w3 * e.z;
    r.w = w0 * a.w + w1 * bb.w + w2 * c.w + w3 * e.w;
    *(float4*)(out + (size_t)b * D_DIM + d) = r;
}

// ---------------------------------------------------------------------------
extern "C" void kernel_launch(void* const* d_in, const int* in_sizes, int n_in,
                              void* d_out, int out_size)
{
    const float* q    = (const float*)d_in[0];
    const float* keys = (const float*)d_in[1];
    const float* vals = (const float*)d_in[2];
    float* out = (float*)d_out;
    (void)in_sizes; (void)n_in; (void)out_size;   // fixed shapes: 16384x1024, 8192x1024, k=4

    float *qinv = nullptr, *kinv = nullptr;
    cudaGetSymbolAddress((void**)&qinv, g_qinv);
    cudaGetSymbolAddress((void**)&kinv, g_kinv);

    rowinv_kernel<<<B_ROWS, 256>>>(q, qinv);
    rowinv_kernel<<<N_KEYS, 256>>>(keys, kinv);

    cudaFuncSetAttribute(simtopk_kernel,
                         cudaFuncAttributeMaxDynamicSharedMemorySize, SMEM_BYTES);
    simtopk_kernel<<<B_ROWS / BM, 256, SMEM_BYTES>>>(q, keys);

    combine_kernel<<<B_ROWS, 256>>>(vals, out);
}

// round 5
// speedup vs baseline: 5.0742x; 5.0742x over previous
#include <cuda_runtime.h>
#include <cuda_bf16.h>
#include <math.h>
#include <stdint.h>

#define D_DIM   1024
#define B_ROWS  16384
#define N_KEYS  8192
#define NCAND   8

// ---------------- stage-1 tiling ----------------
#define BM      128
#define BN      128
#define BK      64
#define KCH     (D_DIM / BK)     // 16
#define NT1     (N_KEYS / BN)    // 64
#define ASTRIDE 72               // bf16 per smem row (144 B: 16B-aligned, conflict-free)
#define ABUF_B  (128 * ASTRIDE * 2)      // 18432 B per buffer (A or B tile)
#define SM_A    0
#define SM_B    (2 * ABUF_B)             // 36864
#define SM_S    (4 * ABUF_B)             // 73728
#define SSTR    129
#define SM_KV   (SM_S + 128 * SSTR * 4)  // 139776
#define SMEM1_BYTES (SM_KV + 512)        // 140288

// ---- scratch (device globals; allocation-free per harness rules) ----
__device__ __nv_bfloat16 g_qb[(size_t)B_ROWS * D_DIM];   // 32 MB
__device__ __nv_bfloat16 g_kb[(size_t)N_KEYS * D_DIM];   // 16 MB
__device__ float g_qinv[B_ROWS];
__device__ float g_kinv[N_KEYS];
__device__ int   g_cand[B_ROWS * NCAND];

// ============================================================================
// helpers
// ============================================================================
__device__ __forceinline__ uint32_t smem_u32(const void* p) {
    uint32_t a;
    asm("{ .reg .u64 t; cvta.to.shared.u64 t, %1; cvt.u32.u64 %0, t; }" : "=r"(a) : "l"(p));
    return a;
}
#define CP_ASYNC16(dst, src) \
    asm volatile("cp.async.cg.shared.global [%0], [%1], 16;" :: "r"(dst), "l"(src) : "memory")

__device__ __forceinline__ void ldm_x4(uint32_t* r, uint32_t addr) {
    asm volatile("ldmatrix.sync.aligned.m8n8.x4.shared.b16 {%0,%1,%2,%3}, [%4];"
        : "=r"(r[0]), "=r"(r[1]), "=r"(r[2]), "=r"(r[3]) : "r"(addr));
}
__device__ __forceinline__ void mma16816(float* c, const uint32_t* a, const uint32_t* b) {
    asm volatile("mma.sync.aligned.m16n8k16.row.col.f32.bf16.bf16.f32 "
        "{%0,%1,%2,%3}, {%4,%5,%6,%7}, {%8,%9}, {%0,%1,%2,%3};"
        : "+f"(c[0]), "+f"(c[1]), "+f"(c[2]), "+f"(c[3])
        : "r"(a[0]), "r"(a[1]), "r"(a[2]), "r"(a[3]), "r"(b[0]), "r"(b[1]));
}

// ============================================================================
// Row inverse-norm
// ============================================================================
__global__ void rowinv_kernel(const float* __restrict__ x, float* __restrict__ inv)
{
    int r = blockIdx.x;
    float4 v = ((const float4*)(x + (size_t)r * D_DIM))[threadIdx.x];
    float ss = v.x * v.x + v.y * v.y + v.z * v.z + v.w * v.w;
    #pragma unroll
    for (int o = 16; o > 0; o >>= 1) ss += __shfl_xor_sync(0xffffffffu, ss, o);
    __shared__ float red[8];
    if ((threadIdx.x & 31) == 0) red[threadIdx.x >> 5] = ss;
    __syncthreads();
    if (threadIdx.x == 0) {
        float t = 0.f;
        #pragma unroll
        for (int i = 0; i < 8; i++) t += red[i];
        inv[r] = 1.0f / fmaxf(sqrtf(t), 1e-12f);
    }
}

// ============================================================================
// fp32 -> bf16
// ============================================================================
__global__ void tobf16_kernel(const float* __restrict__ x, __nv_bfloat16* __restrict__ y)
{
    size_t i = ((size_t)blockIdx.x * 256 + threadIdx.x) * 4;
    float4 v = *(const float4*)(x + i);
    *(__nv_bfloat162*)(y + i)     = __floats2bfloat162_rn(v.x, v.y);
    *(__nv_bfloat162*)(y + i + 2) = __floats2bfloat162_rn(v.z, v.w);
}

// ============================================================================
// Stage 1: bf16 mma.sync GEMM (128x128 tiles) + fused per-row top-8
// 128 CTAs x 256 threads (8 warps, 2Mx4N, warp tile 64x32).
// ============================================================================
__global__ __launch_bounds__(256, 1)
void stage1_kernel()
{
    extern __shared__ char smem[];
    const uint32_t sb = smem_u32(smem);
    const int t    = threadIdx.x;
    const int lane = t & 31;
    const int warp = t >> 5;
    const int mw   = warp >> 2;      // 0..1
    const int nw   = warp & 3;       // 0..3
    const int qbase = blockIdx.x * BM;

    float* Ss = (float*)(smem + SM_S);
    float* kv = (float*)(smem + SM_KV);

    float v[NCAND]; int id8[NCAND];
    #pragma unroll
    for (int j = 0; j < NCAND; j++) { v[j] = -1e30f; id8[j] = 0; }

    // per-thread constant pieces of ldmatrix addresses (bf16-element units)
    const int a_row = (lane & 15);          // + mw*64 + i*16
    const int a_col = (lane >> 4) * 8;      // + ks*16
    const int matid = lane >> 3;
    const int b_row = ((matid >> 1) << 3) + (lane & 7);   // + nw*32 + g*16
    const int b_col = (matid & 1) << 3;                   // + ks*16

    for (int nt = 0; nt < NT1; nt++) {
        const int n0 = nt * BN;

        float acc[4][4][4];
        #pragma unroll
        for (int i = 0; i < 4; i++)
            #pragma unroll
            for (int j = 0; j < 4; j++)
                #pragma unroll
                for (int c = 0; c < 4; c++) acc[i][j][c] = 0.f;

        // ---- prologue load (stage 0, buffer 0) ----
        {
            #pragma unroll
            for (int l = 0; l < 4; l++) {
                int idx = t + l * 256, r = idx >> 3, c = idx & 7;
                CP_ASYNC16(sb + SM_A + r * 144 + c * 16,
                           (const void*)(g_qb + (size_t)(qbase + r) * D_DIM + c * 8));
            }
            #pragma unroll
            for (int l = 0; l < 4; l++) {
                int idx = t + l * 256, r = idx >> 3, c = idx & 7;
                CP_ASYNC16(sb + SM_B + r * 144 + c * 16,
                           (const void*)(g_kb + (size_t)(n0 + r) * D_DIM + c * 8));
            }
            asm volatile("cp.async.commit_group;" ::: "memory");
        }

        for (int kc = 0; kc < KCH; kc++) {
            const int p = kc & 1;
            if (kc + 1 < KCH) {
                const int kt = (kc + 1) * BK;
                const uint32_t ao = sb + SM_A + (1 - p) * ABUF_B;
                const uint32_t bo = sb + SM_B + (1 - p) * ABUF_B;
                #pragma unroll
                for (int l = 0; l < 4; l++) {
                    int idx = t + l * 256, r = idx >> 3, c = idx & 7;
                    CP_ASYNC16(ao + r * 144 + c * 16,
                               (const void*)(g_qb + (size_t)(qbase + r) * D_DIM + kt + c * 8));
                }
                #pragma unroll
                for (int l = 0; l < 4; l++) {
                    int idx = t + l * 256, r = idx >> 3, c = idx & 7;
                    CP_ASYNC16(bo + r * 144 + c * 16,
                               (const void*)(g_kb + (size_t)(n0 + r) * D_DIM + kt + c * 8));
                }
                asm volatile("cp.async.commit_group;" ::: "memory");
                asm volatile("cp.async.wait_group 1;" ::: "memory");
            } else {
                asm volatile("cp.async.wait_group 0;" ::: "memory");
            }
            __syncthreads();

            const uint32_t ab = sb + SM_A + p * ABUF_B;
            const uint32_t bb = sb + SM_B + p * ABUF_B;
            #pragma unroll
            for (int ks = 0; ks < 4; ks++) {
                uint32_t af[4][4];
                #pragma unroll
                for (int i = 0; i < 4; i++) {
                    uint32_t addr = ab + ((mw * 64 + i * 16 + a_row) * ASTRIDE
                                          + a_col + ks * 16) * 2;
                    ldm_x4(af[i], addr);
                }
                uint32_t bf[4][2];
                #pragma unroll
                for (int g = 0; g < 2; g++) {
                    uint32_t r4[4];
                    uint32_t addr = bb + ((nw * 32 + g * 16 + b_row) * ASTRIDE
                                          + b_col + ks * 16) * 2;
                    ldm_x4(r4, addr);
                    bf[2 * g][0] = r4[0]; bf[2 * g][1] = r4[1];
                    bf[2 * g + 1][0] = r4[2]; bf[2 * g + 1][1] = r4[3];
                }
                #pragma unroll
                for (int i = 0; i < 4; i++)
                    #pragma unroll
                    for (int j = 0; j < 4; j++)
                        mma16816(acc[i][j], af[i], bf[j]);
            }
            __syncthreads();   // all reads of buf p done before its refill next iter
        }

        // ---- epilogue: kinv scale -> smem sims -> running top-8 ----
        if (t < 128) kv[t] = __ldg(g_kinv + n0 + t);
        __syncthreads();

        {
            const int g  = lane >> 2;
            const int c2 = (lane & 3) << 1;
            #pragma unroll
            for (int i = 0; i < 4; i++) {
                int r0 = mw * 64 + i * 16 + g;
                #pragma unroll
                for (int j = 0; j < 4; j++) {
                    int c0 = nw * 32 + j * 8 + c2;
                    float k0 = kv[c0], k1 = kv[c0 + 1];
                    Ss[r0 * SSTR + c0]           = acc[i][j][0] * k0;
                    Ss[r0 * SSTR + c0 + 1]       = acc[i][j][1] * k1;
                    Ss[(r0 + 8) * SSTR + c0]     = acc[i][j][2] * k0;
                    Ss[(r0 + 8) * SSTR + c0 + 1] = acc[i][j][3] * k1;
                }
            }
        }
        __syncthreads();

        if (t < 128) {
            const float* rowp = Ss + t * SSTR;
            #pragma unroll 4
            for (int n = 0; n < BN; n++) {
                float s = rowp[n];
                if (s > v[NCAND - 1]) {
                    v[NCAND - 1] = s; id8[NCAND - 1] = n0 + n;
                    #pragma unroll
                    for (int j = NCAND - 1; j > 0; j--) {
                        if (v[j] > v[j - 1]) {
                            float tv = v[j]; v[j] = v[j - 1]; v[j - 1] = tv;
                            int ti = id8[j]; id8[j] = id8[j - 1]; id8[j - 1] = ti;
                        }
                    }
                }
            }
        }
        // scan protected from next nt's sims writes by the K-loop syncthreads
    }

    if (t < 128) {
        #pragma unroll
        for (int j = 0; j < NCAND; j++) g_cand[(qbase + t) * NCAND + j] = id8[j];
    }
}

// ============================================================================
// Stage 2: exact fp32 rescore of 8 candidates + top-4 + softmax + combine
// grid = B_ROWS blocks, 128 threads (warp w -> candidates 2w, 2w+1)
// ============================================================================
__global__ __launch_bounds__(128)
void stage2_kernel(const float* __restrict__ q, const float* __restrict__ keys,
                   const float* __restrict__ vals, float* __restrict__ out)
{
    __shared__ float ssim[NCAND];
    __shared__ int   scand[NCAND];
    __shared__ float sw4[4];
    __shared__ int   sid4[4];

    const int b = blockIdx.x;
    const int t = threadIdx.x, lane = t & 31, w = t >> 5;

    if (t < NCAND) scand[t] = g_cand[b * NCAND + t];
    __syncthreads();

    const int c0 = scand[2 * w], c1 = scand[2 * w + 1];
    const float* qr = q    + (size_t)b  * D_DIM;
    const float* k0 = keys + (size_t)c0 * D_DIM;
    const float* k1 = keys + (size_t)c1 * D_DIM;
    float a0 = 0.f, a1 = 0.f;
    #pragma unroll
    for (int j = 0; j < 8; j++) {
        int off = j * 128 + lane * 4;
        float4 qv = *(const float4*)(qr + off);
        float4 x0 = *(const float4*)(k0 + off);
        float4 x1 = *(const float4*)(k1 + off);
        a0 += qv.x * x0.x + qv.y * x0.y + qv.z * x0.z + qv.w * x0.w;
        a1 += qv.x * x1.x + qv.y * x1.y + qv.z * x1.z + qv.w * x1.w;
    }
    #pragma unroll
    for (int o = 16; o > 0; o >>= 1) {
        a0 += __shfl_xor_sync(0xffffffffu, a0, o);
        a1 += __shfl_xor_sync(0xffffffffu, a1, o);
    }
    if (lane == 0) {
        ssim[2 * w]     = a0 * __ldg(g_kinv + c0);
        ssim[2 * w + 1] = a1 * __ldg(g_kinv + c1);
    }
    __syncthreads();

    if (t == 0) {
        float s[NCAND]; int ci[NCAND]; bool used[NCAND];
        #pragma unroll
        for (int j = 0; j < NCAND; j++) { s[j] = ssim[j]; ci[j] = scand[j]; used[j] = false; }
        float sel_s[4]; int sel_i[4];
        for (int slot = 0; slot < 4; slot++) {
            float best = -1e30f; int bi = 0x7fffffff, bj = 0;
            for (int j = 0; j < NCAND; j++) {
                if (!used[j] && (s[j] > best || (s[j] == best && ci[j] < bi))) {
                    best = s[j]; bi = ci[j]; bj = j;
                }
            }
            used[bj] = true; sel_s[slot] = best; sel_i[slot] = bi;
        }
        float qi = g_qinv[b];
        float e0 = 1.0f;
        float e1 = expf((sel_s[1] - sel_s[0]) * qi);
        float e2 = expf((sel_s[2] - sel_s[0]) * qi);
        float e3 = expf((sel_s[3] - sel_s[0]) * qi);
        float inv = 1.0f / (e0 + e1 + e2 + e3);
        sw4[0] = e0 * inv; sw4[1] = e1 * inv; sw4[2] = e2 * inv; sw4[3] = e3 * inv;
        sid4[0] = sel_i[0]; sid4[1] = sel_i[1]; sid4[2] = sel_i[2]; sid4[3] = sel_i[3];
    }
    __syncthreads();

    const float w0 = sw4[0], w1 = sw4[1], w2 = sw4[2], w3 = sw4[3];
    const float* v0 = vals + (size_t)sid4[0] * D_DIM;
    const float* v1 = vals + (size_t)sid4[1] * D_DIM;
    const float* v2 = vals + (size_t)sid4[2] * D_DIM;
    const float* v3 = vals + (size_t)sid4[3] * D_DIM;
    float* ob = out + (size_t)b * D_DIM;
    #pragma unroll
    for (int h = 0; h < 2; h++) {
        int d = t * 8 + h * 4;
        float4 x0 = *(const float4*)(v0 + d);
        float4 x1 = *(const float4*)(v1 + d);
        float4 x2 = *(const float4*)(v2 + d);
        float4 x3 = *(const float4*)(v3 + d);
        float4 r;
        r.x = w0 * x0.x + w1 * x1.x + w2 * x2.x + w3 * x3.x;
        r.y = w0 * x0.y + w1 * x1.y + w2 * x2.y + w3 * x3.y;
        r.z = w0 * x0.z + w1 * x1.z + w2 * x2.z + w3 * x3.z;
        r.w = w0 * x0.w + w1 * x1.w + w2 * x2.w + w3 * x3.w;
        *(float4*)(ob + d) = r;
    }
}

// ============================================================================
extern "C" void kernel_launch(void* const* d_in, const int* in_sizes, int n_in,
                              void* d_out, int out_size)
{
    const float* q    = (const float*)d_in[0];
    const float* keys = (const float*)d_in[1];
    const float* vals = (const float*)d_in[2];
    float* out = (float*)d_out;
    (void)in_sizes; (void)n_in; (void)out_size;

    float *qinv = nullptr, *kinv = nullptr;
    __nv_bfloat16 *qb = nullptr, *kb = nullptr;
    cudaGetSymbolAddress((void**)&qinv, g_qinv);
    cudaGetSymbolAddress((void**)&kinv, g_kinv);
    cudaGetSymbolAddress((void**)&qb, g_qb);
    cudaGetSymbolAddress((void**)&kb, g_kb);

    rowinv_kernel<<<B_ROWS, 256>>>(q, qinv);
    rowinv_kernel<<<N_KEYS, 256>>>(keys, kinv);
    tobf16_kernel<<<(B_ROWS * (D_DIM / 4)) / 256, 256>>>(q, qb);
    tobf16_kernel<<<(N_KEYS * (D_DIM / 4)) / 256, 256>>>(keys, kb);

    cudaFuncSetAttribute(stage1_kernel,
                         cudaFuncAttributeMaxDynamicSharedMemorySize, SMEM1_BYTES);
    stage1_kernel<<<B_ROWS / BM, 256, SMEM1_BYTES>>>();

    stage2_kernel<<<B_ROWS, 128>>>(q, keys, vals, out);
}

// round 6
// speedup vs baseline: 5.5792x; 1.0995x over previous
#include <cuda_runtime.h>
#include <cuda_bf16.h>
#include <math.h>
#include <stdint.h>

#define D_DIM   1024
#define B_ROWS  16384
#define N_KEYS  8192
#define NCAND   8

// ---------------- stage-1 tiling ----------------
#define BM      128
#define BN      256
#define BK      64
#define KCH     (D_DIM / BK)       // 16
#define NT1     (N_KEYS / BN)      // 32
#define GMAX    (NT1 * KCH)        // 512 flat chunks
#define ASTRIDE 72                 // bf16/row (144 B; 16B-aligned rows, conflict-free ldmatrix)
#define A_BYTES (128 * 144)        // 18432
#define B_BYTES (256 * 144)        // 36864
#define STAGE_B (A_BYTES + B_BYTES)// 55296
#define STAGES  3
#define SM_SS   (STAGES * STAGE_B) // 165888
#define SSTR    129
#define SMEM1_BYTES (SM_SS + 128 * SSTR * 4)   // 231936  (<= 227KB opt-in)

// ---- scratch (device globals; allocation-free per harness rules) ----
__device__ __nv_bfloat16 g_qb[(size_t)B_ROWS * D_DIM];   // 32 MB
__device__ __nv_bfloat16 g_kb[(size_t)N_KEYS * D_DIM];   // 16 MB
__device__ float g_qinv[B_ROWS];
__device__ float g_kinv[N_KEYS];
__device__ int   g_cand[B_ROWS * NCAND];

// ============================================================================
// helpers
// ============================================================================
__device__ __forceinline__ uint32_t smem_u32(const void* p) {
    uint32_t a;
    asm("{ .reg .u64 t; cvta.to.shared.u64 t, %1; cvt.u32.u64 %0, t; }" : "=r"(a) : "l"(p));
    return a;
}
#define CP_ASYNC16(dst, src) \
    asm volatile("cp.async.cg.shared.global [%0], [%1], 16;" :: "r"(dst), "l"(src) : "memory")
#define CP_COMMIT() asm volatile("cp.async.commit_group;" ::: "memory")

__device__ __forceinline__ void ldm_x4(uint32_t* r, uint32_t addr) {
    asm volatile("ldmatrix.sync.aligned.m8n8.x4.shared.b16 {%0,%1,%2,%3}, [%4];"
        : "=r"(r[0]), "=r"(r[1]), "=r"(r[2]), "=r"(r[3]) : "r"(addr));
}
__device__ __forceinline__ void mma16816(float* c, const uint32_t* a, const uint32_t* b) {
    asm volatile("mma.sync.aligned.m16n8k16.row.col.f32.bf16.bf16.f32 "
        "{%0,%1,%2,%3}, {%4,%5,%6,%7}, {%8,%9}, {%0,%1,%2,%3};"
        : "+f"(c[0]), "+f"(c[1]), "+f"(c[2]), "+f"(c[3])
        : "r"(a[0]), "r"(a[1]), "r"(a[2]), "r"(a[3]), "r"(b[0]), "r"(b[1]));
}

// ============================================================================
// Fused prep: fp32 -> bf16 conversion + row inverse-norm (one read of x)
// grid = rows, block = 256 (256 * float4 = 1024 elems)
// ============================================================================
__global__ void prep_kernel(const float* __restrict__ x, __nv_bfloat16* __restrict__ y,
                            float* __restrict__ inv)
{
    int r = blockIdx.x;
    size_t o = (size_t)r * D_DIM + threadIdx.x * 4;
    float4 v = *(const float4*)(x + o);
    *(__nv_bfloat162*)(y + o)     = __floats2bfloat162_rn(v.x, v.y);
    *(__nv_bfloat162*)(y + o + 2) = __floats2bfloat162_rn(v.z, v.w);
    float ss = v.x * v.x + v.y * v.y + v.z * v.z + v.w * v.w;
    #pragma unroll
    for (int off = 16; off > 0; off >>= 1) ss += __shfl_xor_sync(0xffffffffu, ss, off);
    __shared__ float red[8];
    if ((threadIdx.x & 31) == 0) red[threadIdx.x >> 5] = ss;
    __syncthreads();
    if (threadIdx.x == 0) {
        float t = 0.f;
        #pragma unroll
        for (int i = 0; i < 8; i++) t += red[i];
        inv[r] = 1.0f / fmaxf(sqrtf(t), 1e-12f);
    }
}

// ============================================================================
// Stage 1: bf16 mma.sync GEMM (128x256 tiles) + fused per-row top-8
// 128 CTAs x 256 threads (8 warps, 2Mx4N, warp tile 64x64).
// Flat 3-stage cp.async ring over all 512 chunks; ONE sync per chunk.
// ============================================================================
__device__ __forceinline__ void issue_chunk(uint32_t sb, int gi, int qbase)
{
    const int slot = gi % STAGES;
    const uint32_t ab = sb + slot * STAGE_B;
    const uint32_t bb = ab + A_BYTES;
    const int kt = (gi & 15) * BK;
    const int n0 = (gi >> 4) * BN;
    const int t = threadIdx.x;
    #pragma unroll
    for (int l = 0; l < 4; l++) {
        int idx = t + l * 256, r = idx >> 3, c = idx & 7;
        CP_ASYNC16(ab + r * 144 + c * 16,
                   (const void*)(g_qb + (size_t)(qbase + r) * D_DIM + kt + c * 8));
    }
    #pragma unroll
    for (int l = 0; l < 8; l++) {
        int idx = t + l * 256, r = idx >> 3, c = idx & 7;
        CP_ASYNC16(bb + r * 144 + c * 16,
                   (const void*)(g_kb + (size_t)(n0 + r) * D_DIM + kt + c * 8));
    }
    CP_COMMIT();
}

__global__ __launch_bounds__(256, 1)
void stage1_kernel()
{
    extern __shared__ char smem[];
    const uint32_t sb = smem_u32(smem);
    float* Ss = (float*)(smem + SM_SS);

    const int t    = threadIdx.x;
    const int lane = t & 31;
    const int warp = t >> 5;
    const int mw   = warp >> 2;      // 0..1
    const int nw   = warp & 3;       // 0..3
    const int qbase = blockIdx.x * BM;

    // ldmatrix per-thread address pieces (element units)
    const int a_row = (lane & 15);
    const int a_col = (lane >> 4) * 8;
    const int matid = lane >> 3;
    const int b_row = ((matid >> 1) << 3) + (lane & 7);
    const int b_col = (matid & 1) << 3;

    float v[NCAND]; int id8[NCAND];
    #pragma unroll
    for (int j = 0; j < NCAND; j++) { v[j] = -1e30f; id8[j] = 0; }

    float acc[4][8][4];
    #pragma unroll
    for (int i = 0; i < 4; i++)
        #pragma unroll
        for (int j = 0; j < 8; j++)
            #pragma unroll
            for (int c = 0; c < 4; c++) acc[i][j][c] = 0.f;

    // prologue: chunks 0,1 into slots 0,1
    issue_chunk(sb, 0, qbase);
    issue_chunk(sb, 1, qbase);

    for (int g = 0; g < GMAX; g++) {
        if (g == GMAX - 1) { asm volatile("cp.async.wait_group 0;" ::: "memory"); }
        else               { asm volatile("cp.async.wait_group 1;" ::: "memory"); }
        __syncthreads();                      // chunk g visible; chunk g-1 reads done
        if (g + 2 < GMAX) issue_chunk(sb, g + 2, qbase);   // into slot (g-1)%3

        const uint32_t ab = sb + (g % STAGES) * STAGE_B;
        const uint32_t bb = ab + A_BYTES;
        #pragma unroll
        for (int ks = 0; ks < 4; ks++) {
            uint32_t af[4][4];
            #pragma unroll
            for (int i = 0; i < 4; i++)
                ldm_x4(af[i], ab + ((mw * 64 + i * 16 + a_row) * ASTRIDE
                                     + a_col + ks * 16) * 2);
            uint32_t bf[8][2];
            #pragma unroll
            for (int gq = 0; gq < 4; gq++) {
                uint32_t r4[4];
                ldm_x4(r4, bb + ((nw * 64 + gq * 16 + b_row) * ASTRIDE
                                  + b_col + ks * 16) * 2);
                bf[2 * gq][0] = r4[0];     bf[2 * gq][1] = r4[1];
                bf[2 * gq + 1][0] = r4[2]; bf[2 * gq + 1][1] = r4[3];
            }
            #pragma unroll
            for (int i = 0; i < 4; i++)
                #pragma unroll
                for (int j = 0; j < 8; j++)
                    mma16816(acc[i][j], af[i], bf[j]);
        }

        // ---- per-tile epilogue (prefetch keeps flowing underneath) ----
        if ((g & 15) == 15) {
            const int n0 = (g >> 4) * BN;
            #pragma unroll
            for (int h = 0; h < 2; h++) {
                __syncthreads();              // prior scan / compute ordered
                if ((nw >> 1) == h) {         // warps owning this 128-col half
                    #pragma unroll
                    for (int i = 0; i < 4; i++) {
                        int r0 = mw * 64 + i * 16 + (lane >> 2);
                        #pragma unroll
                        for (int j = 0; j < 8; j++) {
                            int cl = (nw & 1) * 64 + j * 8 + (lane & 3) * 2;
                            float k0 = __ldg(g_kinv + n0 + h * 128 + cl);
                            float k1 = __ldg(g_kinv + n0 + h * 128 + cl + 1);
                            Ss[r0 * SSTR + cl]           = acc[i][j][0] * k0;
                            Ss[r0 * SSTR + cl + 1]       = acc[i][j][1] * k1;
                            Ss[(r0 + 8) * SSTR + cl]     = acc[i][j][2] * k0;
                            Ss[(r0 + 8) * SSTR + cl + 1] = acc[i][j][3] * k1;
                        }
                    }
                }
                __syncthreads();
                // all 256 threads scan: 2 threads per row, 64 cols each
                {
                    const int row = t & 127;
                    const int cb  = (t >> 7) * 64;
                    const float* rp = Ss + row * SSTR + cb;
                    const int base_id = n0 + h * 128 + cb;
                    #pragma unroll 4
                    for (int n = 0; n < 64; n++) {
                        float s = rp[n];
                        if (s > v[NCAND - 1]) {
                            v[NCAND - 1] = s; id8[NCAND - 1] = base_id + n;
                            #pragma unroll
                            for (int j = NCAND - 1; j > 0; j--) {
                                if (v[j] > v[j - 1]) {
                                    float tv = v[j]; v[j] = v[j - 1]; v[j - 1] = tv;
                                    int ti = id8[j]; id8[j] = id8[j - 1]; id8[j - 1] = ti;
                                }
                            }
                        }
                    }
                }
            }
            // reset accumulators for next tile
            #pragma unroll
            for (int i = 0; i < 4; i++)
                #pragma unroll
                for (int j = 0; j < 8; j++)
                    #pragma unroll
                    for (int c = 0; c < 4; c++) acc[i][j][c] = 0.f;
        }
    }

    // ---- merge the two half-scanners per row (stable: tie -> lower id) ----
    __syncthreads();
    if (t >= 128) {
        int row = t - 128;
        #pragma unroll
        for (int j = 0; j < NCAND; j++) {
            Ss[row * 8 + j] = v[j];
            ((int*)Ss)[1024 + row * 8 + j] = id8[j];
        }
    }
    __syncthreads();
    if (t < 128) {
        float bv[NCAND]; int bid[NCAND];
        #pragma unroll
        for (int j = 0; j < NCAND; j++) {
            bv[j]  = Ss[t * 8 + j];
            bid[j] = ((int*)Ss)[1024 + t * 8 + j];
        }
        float ov[NCAND]; int oid[NCAND];
        int ai = 0, bi = 0;
        #pragma unroll
        for (int s = 0; s < NCAND; s++) {
            bool lo = (v[ai] > bv[bi]) || (v[ai] == bv[bi] && id8[ai] < bid[bi]);
            if (lo) { ov[s] = v[ai]; oid[s] = id8[ai]; ai++; }
            else    { ov[s] = bv[bi]; oid[s] = bid[bi]; bi++; }
        }
        (void)ov;
        #pragma unroll
        for (int j = 0; j < NCAND; j++) g_cand[(qbase + t) * NCAND + j] = oid[j];
    }
}

// ============================================================================
// Stage 2: exact fp32 rescore of 8 candidates + top-4 + softmax + combine
// grid = B_ROWS blocks, 128 threads (warp w -> candidates 2w, 2w+1)
// ============================================================================
__global__ __launch_bounds__(128)
void stage2_kernel(const float* __restrict__ q, const float* __restrict__ keys,
                   const float* __restrict__ vals, float* __restrict__ out)
{
    __shared__ float ssim[NCAND];
    __shared__ int   scand[NCAND];
    __shared__ float sw4[4];
    __shared__ int   sid4[4];

    const int b = blockIdx.x;
    const int t = threadIdx.x, lane = t & 31, w = t >> 5;

    if (t < NCAND) scand[t] = g_cand[b * NCAND + t];
    __syncthreads();

    const int c0 = scand[2 * w], c1 = scand[2 * w + 1];
    const float* qr = q    + (size_t)b  * D_DIM;
    const float* k0 = keys + (size_t)c0 * D_DIM;
    const float* k1 = keys + (size_t)c1 * D_DIM;
    float a0 = 0.f, a1 = 0.f;
    #pragma unroll
    for (int j = 0; j < 8; j++) {
        int off = j * 128 + lane * 4;
        float4 qv = *(const float4*)(qr + off);
        float4 x0 = *(const float4*)(k0 + off);
        float4 x1 = *(const float4*)(k1 + off);
        a0 += qv.x * x0.x + qv.y * x0.y + qv.z * x0.z + qv.w * x0.w;
        a1 += qv.x * x1.x + qv.y * x1.y + qv.z * x1.z + qv.w * x1.w;
    }
    #pragma unroll
    for (int o = 16; o > 0; o >>= 1) {
        a0 += __shfl_xor_sync(0xffffffffu, a0, o);
        a1 += __shfl_xor_sync(0xffffffffu, a1, o);
    }
    if (lane == 0) {
        ssim[2 * w]     = a0 * __ldg(g_kinv + c0);
        ssim[2 * w + 1] = a1 * __ldg(g_kinv + c1);
    }
    __syncthreads();

    if (t == 0) {
        float s[NCAND]; int ci[NCAND]; bool used[NCAND];
        #pragma unroll
        for (int j = 0; j < NCAND; j++) { s[j] = ssim[j]; ci[j] = scand[j]; used[j] = false; }
        float sel_s[4]; int sel_i[4];
        for (int slot = 0; slot < 4; slot++) {
            float best = -1e30f; int bi = 0x7fffffff, bj = 0;
            for (int j = 0; j < NCAND; j++) {
                if (!used[j] && (s[j] > best || (s[j] == best && ci[j] < bi))) {
                    best = s[j]; bi = ci[j]; bj = j;
                }
            }
            used[bj] = true; sel_s[slot] = best; sel_i[slot] = bi;
        }
        float qi = g_qinv[b];
        float e0 = 1.0f;
        float e1 = expf((sel_s[1] - sel_s[0]) * qi);
        float e2 = expf((sel_s[2] - sel_s[0]) * qi);
        float e3 = expf((sel_s[3] - sel_s[0]) * qi);
        float inv = 1.0f / (e0 + e1 + e2 + e3);
        sw4[0] = e0 * inv; sw4[1] = e1 * inv; sw4[2] = e2 * inv; sw4[3] = e3 * inv;
        sid4[0] = sel_i[0]; sid4[1] = sel_i[1]; sid4[2] = sel_i[2]; sid4[3] = sel_i[3];
    }
    __syncthreads();

    const float w0 = sw4[0], w1 = sw4[1], w2 = sw4[2], w3 = sw4[3];
    const float* v0 = vals + (size_t)sid4[0] * D_DIM;
    const float* v1 = vals + (size_t)sid4[1] * D_DIM;
    const float* v2 = vals + (size_t)sid4[2] * D_DIM;
    const float* v3 = vals + (size_t)sid4[3] * D_DIM;
    float* ob = out + (size_t)b * D_DIM;
    #pragma unroll
    for (int h = 0; h < 2; h++) {
        int d = t * 8 + h * 4;
        float4 x0 = *(const float4*)(v0 + d);
        float4 x1 = *(const float4*)(v1 + d);
        float4 x2 = *(const float4*)(v2 + d);
        float4 x3 = *(const float4*)(v3 + d);
        float4 r;
        r.x = w0 * x0.x + w1 * x1.x + w2 * x2.x + w3 * x3.x;
        r.y = w0 * x0.y + w1 * x1.y + w2 * x2.y + w3 * x3.y;
        r.z = w0 * x0.z + w1 * x1.z + w2 * x2.z + w3 * x3.z;
        r.w = w0 * x0.w + w1 * x1.w + w2 * x2.w + w3 * x3.w;
        *(float4*)(ob + d) = r;
    }
}

// ============================================================================
extern "C" void kernel_launch(void* const* d_in, const int* in_sizes, int n_in,
                              void* d_out, int out_size)
{
    const float* q    = (const float*)d_in[0];
    const float* keys = (const float*)d_in[1];
    const float* vals = (const float*)d_in[2];
    float* out = (float*)d_out;
    (void)in_sizes; (void)n_in; (void)out_size;

    float *qinv = nullptr, *kinv = nullptr;
    __nv_bfloat16 *qb = nullptr, *kb = nullptr;
    cudaGetSymbolAddress((void**)&qinv, g_qinv);
    cudaGetSymbolAddress((void**)&kinv, g_kinv);
    cudaGetSymbolAddress((void**)&qb, g_qb);
    cudaGetSymbolAddress((void**)&kb, g_kb);

    prep_kernel<<<B_ROWS, 256>>>(q, qb, qinv);
    prep_kernel<<<N_KEYS, 256>>>(keys, kb, kinv);

    cudaFuncSetAttribute(stage1_kernel,
                         cudaFuncAttributeMaxDynamicSharedMemorySize, SMEM1_BYTES);
    stage1_kernel<<<B_ROWS / BM, 256, SMEM1_BYTES>>>();

    stage2_kernel<<<B_ROWS, 128>>>(q, keys, vals, out);
}

// round 8
// speedup vs baseline: 5.6979x; 1.0213x over previous
#include <cuda_runtime.h>
#include <cuda_bf16.h>
#include <cuda_fp8.h>
#include <math.h>
#include <stdint.h>

#define D_DIM   1024
#define B_ROWS  16384
#define N_KEYS  8192
#define NCAND   8          // per half-scanner
#define NCTOT   16         // union emitted to stage 2

// ---------------- stage-1 tiling (fp8) ----------------
#define BM      128
#define BN      256
#define BK      64                  // 64 fp8 = 64 B per row-chunk
#define KCH     (D_DIM / BK)        // 16
#define NT1     (N_KEYS / BN)       // 32
#define GMAX    (NT1 * KCH)         // 512 flat chunks
#define RSTRIDE 80                  // bytes per smem row (16B-aligned, conflict-free)
#define A_BYTES (128 * RSTRIDE)     // 10240
#define B_BYTES (256 * RSTRIDE)     // 20480
#define STAGE_B (A_BYTES + B_BYTES) // 30720
#define STAGES  3
#define SM_SS   (STAGES * STAGE_B)  // 92160
#define SSTR    129
#define SMEM1_BYTES (SM_SS + 128 * SSTR * 4)   // 158208

// ---- scratch (device globals; allocation-free per harness rules) ----
__device__ __nv_fp8_e4m3 g_q8[(size_t)B_ROWS * D_DIM];   // 16 MB
__device__ __nv_fp8_e4m3 g_k8[(size_t)N_KEYS * D_DIM];   // 8 MB
__device__ float g_qinv[B_ROWS];
__device__ float g_kinv[N_KEYS];
__device__ int   g_cand[B_ROWS * NCTOT];

// ============================================================================
// helpers
// ============================================================================
__device__ __forceinline__ uint32_t smem_u32(const void* p) {
    uint32_t a;
    asm("{ .reg .u64 t; cvta.to.shared.u64 t, %1; cvt.u32.u64 %0, t; }" : "=r"(a) : "l"(p));
    return a;
}
#define CP_ASYNC16(dst, src) \
    asm volatile("cp.async.cg.shared.global [%0], [%1], 16;" :: "r"(dst), "l"(src) : "memory")
#define CP_COMMIT() asm volatile("cp.async.commit_group;" ::: "memory")

__device__ __forceinline__ void ldm_x4(uint32_t* r, uint32_t addr) {
    asm volatile("ldmatrix.sync.aligned.m8n8.x4.shared.b16 {%0,%1,%2,%3}, [%4];"
        : "=r"(r[0]), "=r"(r[1]), "=r"(r[2]), "=r"(r[3]) : "r"(addr));
}
// fp8 e4m3 MMA: D[16x8] += A[16x32] * B[32x8], fp32 accum
__device__ __forceinline__ void mma16832(float* c, const uint32_t* a, const uint32_t* b) {
    asm volatile("mma.sync.aligned.m16n8k32.row.col.f32.e4m3.e4m3.f32 "
        "{%0,%1,%2,%3}, {%4,%5,%6,%7}, {%8,%9}, {%0,%1,%2,%3};"
        : "+f"(c[0]), "+f"(c[1]), "+f"(c[2]), "+f"(c[3])
        : "r"(a[0]), "r"(a[1]), "r"(a[2]), "r"(a[3]), "r"(b[0]), "r"(b[1]));
}

// ============================================================================
// Fused prep: fp32 -> fp8 e4m3 + row inverse-norm (single read of x)
// ============================================================================
__global__ void prep_kernel(const float* __restrict__ x, __nv_fp8_e4m3* __restrict__ y,
                            float* __restrict__ inv)
{
    int r = blockIdx.x;
    size_t o = (size_t)r * D_DIM + threadIdx.x * 4;
    float4 v = *(const float4*)(x + o);
    *(__nv_fp8x4_e4m3*)(y + o) = __nv_fp8x4_e4m3(v);
    float ss = v.x * v.x + v.y * v.y + v.z * v.z + v.w * v.w;
    #pragma unroll
    for (int off = 16; off > 0; off >>= 1) ss += __shfl_xor_sync(0xffffffffu, ss, off);
    __shared__ float red[8];
    if ((threadIdx.x & 31) == 0) red[threadIdx.x >> 5] = ss;
    __syncthreads();
    if (threadIdx.x == 0) {
        float t = 0.f;
        #pragma unroll
        for (int i = 0; i < 8; i++) t += red[i];
        inv[r] = 1.0f / fmaxf(sqrtf(t), 1e-12f);
    }
}

// ============================================================================
// Stage 1: fp8 mma.sync GEMM (128x256 tiles) + per-row top-8 per column-half
// 128 CTAs x 256 threads (8 warps, 2Mx4N, warp tile 64x64).
// Flat 3-stage cp.async ring over all 512 chunks; one sync per chunk.
// ============================================================================
__device__ __forceinline__ void issue_chunk(uint32_t sb, int gi, int qbase)
{
    const int slot = gi % STAGES;
    const uint32_t ab = sb + slot * STAGE_B;
    const uint32_t bb = ab + A_BYTES;
    const int kt = (gi & 15) * BK;
    const int n0 = (gi >> 4) * BN;
    const int t = threadIdx.x;
    #pragma unroll
    for (int l = 0; l < 2; l++) {                    // A: 128 rows x 4 sixteens
        int idx = t + l * 256, r = idx >> 2, c = idx & 3;
        CP_ASYNC16(ab + r * RSTRIDE + c * 16,
                   (const void*)(g_q8 + (size_t)(qbase + r) * D_DIM + kt + c * 16));
    }
    #pragma unroll
    for (int l = 0; l < 4; l++) {                    // B: 256 rows x 4 sixteens
        int idx = t + l * 256, r = idx >> 2, c = idx & 3;
        CP_ASYNC16(bb + r * RSTRIDE + c * 16,
                   (const void*)(g_k8 + (size_t)(n0 + r) * D_DIM + kt + c * 16));
    }
    CP_COMMIT();
}

__global__ __launch_bounds__(256, 1)
void stage1_kernel()
{
    extern __shared__ char smem[];
    const uint32_t sb = smem_u32(smem);
    float* Ss = (float*)(smem + SM_SS);

    const int t    = threadIdx.x;
    const int lane = t & 31;
    const int warp = t >> 5;
    const int mw   = warp >> 2;      // 0..1
    const int nw   = warp & 3;       // 0..3
    const int qbase = blockIdx.x * BM;

    // ldmatrix per-thread address pieces
    const int a_row = (lane & 15);              // + mw*64 + i*16
    const int a_cB  = (lane >> 4) * 16;         // byte col half (+ ks*32)
    const int matid = lane >> 3;
    const int b_row = ((matid >> 1) << 3) + (lane & 7);   // + nw*64 + gq*16
    const int b_cB  = (matid & 1) * 16;                   // byte col (+ ks*32)

    float v[NCAND]; int id8[NCAND];
    #pragma unroll
    for (int j = 0; j < NCAND; j++) { v[j] = -1e30f; id8[j] = 0; }

    float acc[4][8][4];
    #pragma unroll
    for (int i = 0; i < 4; i++)
        #pragma unroll
        for (int j = 0; j < 8; j++)
            #pragma unroll
            for (int c = 0; c < 4; c++) acc[i][j][c] = 0.f;

    issue_chunk(sb, 0, qbase);
    issue_chunk(sb, 1, qbase);

    for (int g = 0; g < GMAX; g++) {
        if (g == GMAX - 1) { asm volatile("cp.async.wait_group 0;" ::: "memory"); }
        else               { asm volatile("cp.async.wait_group 1;" ::: "memory"); }
        __syncthreads();
        if (g + 2 < GMAX) issue_chunk(sb, g + 2, qbase);

        const uint32_t ab = sb + (g % STAGES) * STAGE_B;
        const uint32_t bb = ab + A_BYTES;
        #pragma unroll
        for (int ks = 0; ks < 2; ks++) {            // two k32 steps per 64-chunk
            uint32_t af[4][4];
            #pragma unroll
            for (int i = 0; i < 4; i++)
                ldm_x4(af[i], ab + (mw * 64 + i * 16 + a_row) * RSTRIDE
                                 + a_cB + ks * 32);
            uint32_t bf[8][2];
            #pragma unroll
            for (int gq = 0; gq < 4; gq++) {
                uint32_t r4[4];
                ldm_x4(r4, bb + (nw * 64 + gq * 16 + b_row) * RSTRIDE
                              + b_cB + ks * 32);
                bf[2 * gq][0] = r4[0];     bf[2 * gq][1] = r4[1];
                bf[2 * gq + 1][0] = r4[2]; bf[2 * gq + 1][1] = r4[3];
            }
            #pragma unroll
            for (int i = 0; i < 4; i++)
                #pragma unroll
                for (int j = 0; j < 8; j++)
                    mma16832(acc[i][j], af[i], bf[j]);
        }

        // ---- per-tile epilogue ----
        if ((g & 15) == 15) {
            const int n0 = (g >> 4) * BN;
            #pragma unroll
            for (int h = 0; h < 2; h++) {
                __syncthreads();
                if ((nw >> 1) == h) {
                    #pragma unroll
                    for (int i = 0; i < 4; i++) {
                        int r0 = mw * 64 + i * 16 + (lane >> 2);
                        #pragma unroll
                        for (int j = 0; j < 8; j++) {
                            int cl = (nw & 1) * 64 + j * 8 + (lane & 3) * 2;
                            float k0 = __ldg(g_kinv + n0 + h * 128 + cl);
                            float k1 = __ldg(g_kinv + n0 + h * 128 + cl + 1);
                            Ss[r0 * SSTR + cl]           = acc[i][j][0] * k0;
                            Ss[r0 * SSTR + cl + 1]       = acc[i][j][1] * k1;
                            Ss[(r0 + 8) * SSTR + cl]     = acc[i][j][2] * k0;
                            Ss[(r0 + 8) * SSTR + cl + 1] = acc[i][j][3] * k1;
                        }
                    }
                }
                __syncthreads();
                {   // 2 threads per row, 64 cols each; halves stay separate
                    const int row = t & 127;
                    const int cb  = (t >> 7) * 64;
                    const float* rp = Ss + row * SSTR + cb;
                    const int base_id = n0 + h * 128 + cb;
                    #pragma unroll 4
                    for (int n = 0; n < 64; n++) {
                        float s = rp[n];
                        if (s > v[NCAND - 1]) {
                            v[NCAND - 1] = s; id8[NCAND - 1] = base_id + n;
                            #pragma unroll
                            for (int j = NCAND - 1; j > 0; j--) {
                                if (v[j] > v[j - 1]) {
                                    float tv = v[j]; v[j] = v[j - 1]; v[j - 1] = tv;
                                    int ti = id8[j]; id8[j] = id8[j - 1]; id8[j - 1] = ti;
                                }
                            }
                        }
                    }
                }
            }
            #pragma unroll
            for (int i = 0; i < 4; i++)
                #pragma unroll
                for (int j = 0; j < 8; j++)
                    #pragma unroll
                    for (int c = 0; c < 4; c++) acc[i][j][c] = 0.f;
        }
    }

    // ---- emit union of the two half-scanners: 16 candidates, no merge ----
    {
        int row  = t & 127;
        int half = t >> 7;
        int* dst = g_cand + (size_t)(qbase + row) * NCTOT + half * NCAND;
        #pragma unroll
        for (int j = 0; j < NCAND; j++) dst[j] = id8[j];
    }
}

// ============================================================================
// Stage 2: exact fp32 rescore of 16 candidates + top-4 + softmax + combine
// grid = B_ROWS blocks, 128 threads (warp w -> candidates 4w..4w+3)
// ============================================================================
__global__ __launch_bounds__(128)
void stage2_kernel(const float* __restrict__ q, const float* __restrict__ keys,
                   const float* __restrict__ vals, float* __restrict__ out)
{
    __shared__ float ssim[NCTOT];
    __shared__ int   scand[NCTOT];
    __shared__ float sw4[4];
    __shared__ int   sid4[4];

    const int b = blockIdx.x;
    const int t = threadIdx.x, lane = t & 31, w = t >> 5;

    if (t < NCTOT) scand[t] = g_cand[(size_t)b * NCTOT + t];
    __syncthreads();

    int ci4[4];
    const float* kp[4];
    #pragma unroll
    for (int i = 0; i < 4; i++) {
        ci4[i] = scand[4 * w + i];
        kp[i]  = keys + (size_t)ci4[i] * D_DIM;
    }
    const float* qr = q + (size_t)b * D_DIM;
    float a4[4] = {0.f, 0.f, 0.f, 0.f};
    #pragma unroll
    for (int j = 0; j < 8; j++) {
        int off = j * 128 + lane * 4;
        float4 qv = *(const float4*)(qr + off);
        #pragma unroll
        for (int i = 0; i < 4; i++) {
            float4 kv = *(const float4*)(kp[i] + off);
            a4[i] += qv.x * kv.x + qv.y * kv.y + qv.z * kv.z + qv.w * kv.w;
        }
    }
    #pragma unroll
    for (int o = 16; o > 0; o >>= 1)
        #pragma unroll
        for (int i = 0; i < 4; i++)
            a4[i] += __shfl_xor_sync(0xffffffffu, a4[i], o);
    if (lane == 0) {
        #pragma unroll
        for (int i = 0; i < 4; i++)
            ssim[4 * w + i] = a4[i] * __ldg(g_kinv + ci4[i]);
    }
    __syncthreads();

    if (t == 0) {
        float s[NCTOT]; int ci[NCTOT]; bool used[NCTOT];
        #pragma unroll
        for (int j = 0; j < NCTOT; j++) { s[j] = ssim[j]; ci[j] = scand[j]; used[j] = false; }
        float sel_s[4]; int sel_i[4];
        for (int slot = 0; slot < 4; slot++) {
            float best = -1e30f; int bi = 0x7fffffff, bj = 0;
            for (int j = 0; j < NCTOT; j++) {
                if (!used[j] && (s[j] > best || (s[j] == best && ci[j] < bi))) {
                    best = s[j]; bi = ci[j]; bj = j;
                }
            }
            used[bj] = true; sel_s[slot] = best; sel_i[slot] = bi;
        }
        float qi = g_qinv[b];
        float e0 = 1.0f;
        float e1 = expf((sel_s[1] - sel_s[0]) * qi);
        float e2 = expf((sel_s[2] - sel_s[0]) * qi);
        float e3 = expf((sel_s[3] - sel_s[0]) * qi);
        float inv = 1.0f / (e0 + e1 + e2 + e3);
        sw4[0] = e0 * inv; sw4[1] = e1 * inv; sw4[2] = e2 * inv; sw4[3] = e3 * inv;
        sid4[0] = sel_i[0]; sid4[1] = sel_i[1]; sid4[2] = sel_i[2]; sid4[3] = sel_i[3];
    }
    __syncthreads();

    const float w0 = sw4[0], w1 = sw4[1], w2 = sw4[2], w3 = sw4[3];
    const float* v0 = vals + (size_t)sid4[0] * D_DIM;
    const float* v1 = vals + (size_t)sid4[1] * D_DIM;
    const float* v2 = vals + (size_t)sid4[2] * D_DIM;
    const float* v3 = vals + (size_t)sid4[3] * D_DIM;
    float* ob = out + (size_t)b * D_DIM;
    #pragma unroll
    for (int h = 0; h < 2; h++) {
        int d = t * 8 + h * 4;
        float4 x0 = *(const float4*)(v0 + d);
        float4 x1 = *(const float4*)(v1 + d);
        float4 x2 = *(const float4*)(v2 + d);
        float4 x3 = *(const float4*)(v3 + d);
        float4 r;
        r.x = w0 * x0.x + w1 * x1.x + w2 * x2.x + w3 * x3.x;
        r.y = w0 * x0.y + w1 * x1.y + w2 * x2.y + w3 * x3.y;
        r.z = w0 * x0.z + w1 * x1.z + w2 * x2.z + w3 * x3.z;
        r.w = w0 * x0.w + w1 * x1.w + w2 * x2.w + w3 * x3.w;
        *(float4*)(ob + d) = r;
    }
}

// ============================================================================
extern "C" void kernel_launch(void* const* d_in, const int* in_sizes, int n_in,
                              void* d_out, int out_size)
{
    const float* q    = (const float*)d_in[0];
    const float* keys = (const float*)d_in[1];
    const float* vals = (const float*)d_in[2];
    float* out = (float*)d_out;
    (void)in_sizes; (void)n_in; (void)out_size;

    float *qinv = nullptr, *kinv = nullptr;
    __nv_fp8_e4m3 *q8 = nullptr, *k8 = nullptr;
    cudaGetSymbolAddress((void**)&qinv, g_qinv);
    cudaGetSymbolAddress((void**)&kinv, g_kinv);
    cudaGetSymbolAddress((void**)&q8, g_q8);
    cudaGetSymbolAddress((void**)&k8, g_k8);

    prep_kernel<<<B_ROWS, 256>>>(q, q8, qinv);
    prep_kernel<<<N_KEYS, 256>>>(keys, k8, kinv);

    cudaFuncSetAttribute(stage1_kernel,
                         cudaFuncAttributeMaxDynamicSharedMemorySize, SMEM1_BYTES);
    stage1_kernel<<<B_ROWS / BM, 256, SMEM1_BYTES>>>();

    stage2_kernel<<<B_ROWS, 128>>>(q, keys, vals, out);
}